// round 2
// baseline (speedup 1.0000x reference)
#include <cuda_runtime.h>
#include <cstdint>

// Problem: 3x3 erode+dilate (min/max sliding window, replicate-border == reduce
// over valid pixels), x = (8, 32, 512, 512) fp32. Output = concat(dilated, eroded).
#define IMGS    256        // 8 * 32
#define H       512
#define W       512
#define TILE_H  64
#define THREADS 128        // W / 4 (one float4 per thread; block spans full row)

__device__ __forceinline__ float pinf()  { return __int_as_float(0x7f800000); }
__device__ __forceinline__ float ninf()  { return __int_as_float(0xff800000); }

__global__ void __launch_bounds__(THREADS, 8)
morph3x3_kernel(const float* __restrict__ x, float* __restrict__ out)
{
    const int t   = threadIdx.x;
    const int img = blockIdx.y;
    const int y0  = blockIdx.x * TILE_H;

    const size_t ioff = (size_t)img * H * W;
    const float* base = x + ioff;
    float* dil = out + ioff;                         // dilated = output[0]
    float* ero = out + (size_t)IMGS * H * W + ioff;  // eroded  = output[1]

    const bool has_l = (t > 0);
    const bool has_r = (t < THREADS - 1);

    // Horizontal 3-window min/max of row r; identities for out-of-range rows.
    // Halo scalars fetched directly from global (hit L1/L2; same sectors as the
    // vector loads of neighboring threads -> no extra DRAM traffic, no barriers).
    auto load_h = [&](int r, float4& mx, float4& mn) {
        if (r < 0 || r >= H) {
            mx = make_float4(ninf(), ninf(), ninf(), ninf());
            mn = make_float4(pinf(), pinf(), pinf(), pinf());
            return;                           // r is block-uniform -> uniform branch
        }
        const float* row = base + (size_t)r * W;
        const float4 v = __ldg(((const float4*)row) + t);
        float lmax = ninf(), lmin = pinf(), rmax = ninf(), rmin = pinf();
        if (has_l) { float l = __ldg(row + 4 * t - 1); lmax = l; lmin = l; }
        if (has_r) { float q = __ldg(row + 4 * t + 4); rmax = q; rmin = q; }

        mx.x = fmaxf(lmax, fmaxf(v.x, v.y));
        mx.y = fmaxf(v.x,  fmaxf(v.y, v.z));
        mx.z = fmaxf(v.y,  fmaxf(v.z, v.w));
        mx.w = fmaxf(fmaxf(v.z, v.w), rmax);

        mn.x = fminf(lmin, fminf(v.x, v.y));
        mn.y = fminf(v.x,  fminf(v.y, v.z));
        mn.z = fminf(v.y,  fminf(v.z, v.w));
        mn.w = fminf(fminf(v.z, v.w), rmin);
    };

    // Rolling vertical 3-window: h(r-1), h(r), h(r+1); each input row read once.
    float4 mx_m1, mn_m1, mx_0, mn_0, mx_p1, mn_p1;
    load_h(y0 - 1, mx_m1, mn_m1);
    load_h(y0,     mx_0,  mn_0);

    #pragma unroll 4
    for (int r = y0; r < y0 + TILE_H; ++r) {
        load_h(r + 1, mx_p1, mn_p1);

        float4 dmx, dmn;
        dmx.x = fmaxf(mx_m1.x, fmaxf(mx_0.x, mx_p1.x));
        dmx.y = fmaxf(mx_m1.y, fmaxf(mx_0.y, mx_p1.y));
        dmx.z = fmaxf(mx_m1.z, fmaxf(mx_0.z, mx_p1.z));
        dmx.w = fmaxf(mx_m1.w, fmaxf(mx_0.w, mx_p1.w));

        dmn.x = fminf(mn_m1.x, fminf(mn_0.x, mn_p1.x));
        dmn.y = fminf(mn_m1.y, fminf(mn_0.y, mn_p1.y));
        dmn.z = fminf(mn_m1.z, fminf(mn_0.z, mn_p1.z));
        dmn.w = fminf(mn_m1.w, fminf(mn_0.w, mn_p1.w));

        ((float4*)(dil + (size_t)r * W))[t] = dmx;
        ((float4*)(ero + (size_t)r * W))[t] = dmn;

        mx_m1 = mx_0; mn_m1 = mn_0;
        mx_0  = mx_p1; mn_0 = mn_p1;
    }
}

extern "C" void kernel_launch(void* const* d_in, const int* in_sizes, int n_in,
                              void* d_out, int out_size)
{
    const float* x = (const float*)d_in[0];
    float* out = (float*)d_out;
    dim3 grid(H / TILE_H, IMGS);
    morph3x3_kernel<<<grid, THREADS>>>(x, out);
}

// round 5
// speedup vs baseline: 1.1248x; 1.1248x over previous
#include <cuda_runtime.h>
#include <cstdint>

// 3x3 erode+dilate (min/max window, replicate border == reduce over valid px).
// x = (8, 32, 512, 512) fp32. Output = concat(dilated, eroded).
#define IMGS    256
#define H       512
#define W       512
#define TILE_H  32
#define THREADS 128        // one float4 per thread; block spans the full 512-px row

__device__ __forceinline__ float pinf() { return __int_as_float(0x7f800000); }
__device__ __forceinline__ float ninf() { return __int_as_float(0xff800000); }

__global__ void __launch_bounds__(THREADS, 10)
morph3x3_kernel(const float* __restrict__ x, float* __restrict__ out)
{
    const int t    = threadIdx.x;
    const int lane = t & 31;
    const int img  = blockIdx.y;
    const int y0   = blockIdx.x * TILE_H;

    const size_t ioff = (size_t)img * H * W;
    const float* base = x + ioff;
    float* dil = out + ioff;                         // dilated = output[0]
    float* ero = out + (size_t)IMGS * H * W + ioff;  // eroded  = output[1]

    const bool has_l = (t > 0);
    const bool has_r = (t < THREADS - 1);
    // Cross-warp halo: lane 0 needs row[4t-1], lane 31 needs row[4t+4].
    const bool needs_b = (lane == 0 && has_l) || (lane == 31 && has_r);
    const int  boff    = (lane == 0) ? (4 * t - 1) : (4 * t + 4);

    // Raw row fetch: one LDG.128 + (2 lanes/warp) one predicated scalar LDG.
    auto fetch = [&](int r, float4& v, float& bh) {
        if ((unsigned)r < H) {                       // block-uniform branch
            const float* row = base + (size_t)r * W;
            v = __ldg(((const float4*)row) + t);
            if (needs_b) bh = __ldg(row + boff);
        }
    };

    // Horizontal 3-window min/max; halos via lane shuffle.
    auto hred = [&](int r, const float4 v, const float bh, float4& mx, float4& mn) {
        if ((unsigned)r >= H) {
            mx = make_float4(ninf(), ninf(), ninf(), ninf());
            mn = make_float4(pinf(), pinf(), pinf(), pinf());
            return;
        }
        float l  = __shfl_up_sync(0xffffffffu, v.w, 1);
        float rr = __shfl_down_sync(0xffffffffu, v.x, 1);
        if (lane == 0)  l  = bh;   // garbage if t==0, masked by has_l below
        if (lane == 31) rr = bh;   // garbage if t==127, masked by has_r below

        const float lmax = has_l ? l  : ninf();
        const float lmin = has_l ? l  : pinf();
        const float rmax = has_r ? rr : ninf();
        const float rmin = has_r ? rr : pinf();

        mx.x = fmaxf(lmax, fmaxf(v.x, v.y));
        mx.y = fmaxf(v.x,  fmaxf(v.y, v.z));
        mx.z = fmaxf(v.y,  fmaxf(v.z, v.w));
        mx.w = fmaxf(fmaxf(v.z, v.w), rmax);

        mn.x = fminf(lmin, fminf(v.x, v.y));
        mn.y = fminf(v.x,  fminf(v.y, v.z));
        mn.z = fminf(v.y,  fminf(v.z, v.w));
        mn.w = fminf(fminf(v.z, v.w), rmin);
    };

    // Prologue: h(y0-1), h(y0); prefetch raw row y0+1.
    float4 vA; float bA = 0.f;
    float4 vB; float bB = 0.f;
    float4 mx_m1, mn_m1, mx_0, mn_0, mx_p1, mn_p1;

    fetch(y0 - 1, vA, bA);
    fetch(y0,     vB, bB);
    hred(y0 - 1, vA, bA, mx_m1, mn_m1);
    hred(y0,     vB, bB, mx_0,  mn_0);

    float4 v_cur; float b_cur = 0.f;
    fetch(y0 + 1, v_cur, b_cur);

    #pragma unroll 8
    for (int r = y0; r < y0 + TILE_H; ++r) {
        // Prefetch raw row r+2 (skip past-the-tile fetch on the last iter).
        float4 v_nxt; float b_nxt = 0.f;
        const int rp = (r + 2 <= y0 + TILE_H) ? (r + 2) : -1;
        fetch(rp, v_nxt, b_nxt);

        hred(r + 1, v_cur, b_cur, mx_p1, mn_p1);

        float4 dmx, dmn;
        dmx.x = fmaxf(mx_m1.x, fmaxf(mx_0.x, mx_p1.x));
        dmx.y = fmaxf(mx_m1.y, fmaxf(mx_0.y, mx_p1.y));
        dmx.z = fmaxf(mx_m1.z, fmaxf(mx_0.z, mx_p1.z));
        dmx.w = fmaxf(mx_m1.w, fmaxf(mx_0.w, mx_p1.w));

        dmn.x = fminf(mn_m1.x, fminf(mn_0.x, mn_p1.x));
        dmn.y = fminf(mn_m1.y, fminf(mn_0.y, mn_p1.y));
        dmn.z = fminf(mn_m1.z, fminf(mn_0.z, mn_p1.z));
        dmn.w = fminf(mn_m1.w, fminf(mn_0.w, mn_p1.w));

        __stcs(((float4*)(dil + (size_t)r * W)) + t, dmx);
        __stcs(((float4*)(ero + (size_t)r * W)) + t, dmn);

        mx_m1 = mx_0;  mn_m1 = mn_0;
        mx_0  = mx_p1; mn_0  = mn_p1;
        v_cur = v_nxt; b_cur = b_nxt;
    }
}

extern "C" void kernel_launch(void* const* d_in, const int* in_sizes, int n_in,
                              void* d_out, int out_size)
{
    const float* x = (const float*)d_in[0];
    float* out = (float*)d_out;
    dim3 grid(H / TILE_H, IMGS);
    morph3x3_kernel<<<grid, THREADS>>>(x, out);
}